// round 1
// baseline (speedup 1.0000x reference)
#include <cuda_runtime.h>
#include <cuda_bf16.h>
#include <math.h>

// Problem constants (fixed shapes from setup_inputs)
#define BATCH   4
#define N1      4096
#define N2      16384
#define D1      512
#define D2      256
#define DO      256
#define M1      (BATCH * N1)   // 16384
#define M2      (BATCH * N2)   // 65536

// Scratch for feats1 [B, N1, DO] fp32 = 16 MB (L2-resident)
__device__ float g_feats1[M1 * DO];

// ---------------------------------------------------------------------------
// Fused GEMM + BatchNorm(eval) + ReLU
// C[m, n] = relu( (sum_k A[m,k]*W[n,k] + bias[n]) * s[n] + sh[n] )
//   s  = gamma / sqrt(var + 1e-5),  sh = beta - mean * s
// Tiling: BM=128, BN=64, BK=16, thread tile 8x4, 256 threads.
// ---------------------------------------------------------------------------
#define BM 128
#define BN 64
#define BK 16
#define TM 8
#define TN 4

__global__ __launch_bounds__(256)
void gemm_bn_relu_kernel(const float* __restrict__ A,
                         const float* __restrict__ W,
                         const float* __restrict__ bias,
                         const float* __restrict__ gamma,
                         const float* __restrict__ beta,
                         const float* __restrict__ mean,
                         const float* __restrict__ var,
                         float* __restrict__ C,
                         int M, int K)
{
    __shared__ float As[BK][BM + 4];
    __shared__ float Ws[BK][BN];

    const int bm  = blockIdx.x * BM;
    const int bn  = blockIdx.y * BN;
    const int tid = threadIdx.x;
    const int tx  = tid & 15;   // N direction: 16 * TN = 64
    const int ty  = tid >> 4;   // M direction: 16 * TM = 128

    float acc[TM][TN];
#pragma unroll
    for (int i = 0; i < TM; i++)
#pragma unroll
        for (int j = 0; j < TN; j++) acc[i][j] = 0.f;

    for (int k0 = 0; k0 < K; k0 += BK) {
        // Load A tile (BM x BK) as float4, store transposed into As[k][m]
#pragma unroll
        for (int l = 0; l < 2; l++) {
            int idx = tid + l * 256;          // 0..511
            int row = idx >> 2;               // 0..127
            int kc  = (idx & 3) << 2;         // 0,4,8,12
            float4 v = *(const float4*)&A[(size_t)(bm + row) * K + k0 + kc];
            As[kc + 0][row] = v.x;
            As[kc + 1][row] = v.y;
            As[kc + 2][row] = v.z;
            As[kc + 3][row] = v.w;
        }
        // Load W tile (BN x BK) as float4, store transposed into Ws[k][n]
        {
            int row = tid >> 2;               // 0..63
            int kc  = (tid & 3) << 2;
            float4 v = *(const float4*)&W[(size_t)(bn + row) * K + k0 + kc];
            Ws[kc + 0][row] = v.x;
            Ws[kc + 1][row] = v.y;
            Ws[kc + 2][row] = v.z;
            Ws[kc + 3][row] = v.w;
        }
        __syncthreads();

#pragma unroll
        for (int k = 0; k < BK; k++) {
            float a[TM], w[TN];
#pragma unroll
            for (int i = 0; i < TM; i++) a[i] = As[k][ty * TM + i];
#pragma unroll
            for (int j = 0; j < TN; j++) w[j] = Ws[k][tx * TN + j];
#pragma unroll
            for (int i = 0; i < TM; i++)
#pragma unroll
                for (int j = 0; j < TN; j++)
                    acc[i][j] = fmaf(a[i], w[j], acc[i][j]);
        }
        __syncthreads();
    }

    // Epilogue: bias + BN(eval) + ReLU, vectorized float4 stores
    float s[TN], sh[TN], bb[TN];
#pragma unroll
    for (int j = 0; j < TN; j++) {
        int n = bn + tx * TN + j;
        float sc = gamma[n] * rsqrtf(var[n] + 1e-5f);
        s[j]  = sc;
        sh[j] = beta[n] - mean[n] * sc;
        bb[j] = bias[n];
    }
#pragma unroll
    for (int i = 0; i < TM; i++) {
        int m = bm + ty * TM + i;
        float4 o;
        o.x = fmaxf((acc[i][0] + bb[0]) * s[0] + sh[0], 0.f);
        o.y = fmaxf((acc[i][1] + bb[1]) * s[1] + sh[1], 0.f);
        o.z = fmaxf((acc[i][2] + bb[2]) * s[2] + sh[2], 0.f);
        o.w = fmaxf((acc[i][3] + bb[3]) * s[3] + sh[3], 0.f);
        *(float4*)&C[(size_t)m * DO + bn + tx * TN] = o;
    }
}

// ---------------------------------------------------------------------------
// Fused 3-NN + inverse-distance-weighted gather + accumulate.
// Phase 1: one thread per target; scan all N1 sources held in smem as
//          (-2x, -2y, -2z, ||s||^2) float4; rank key = ||s||^2 - 2 t.s
//          (per-target ||t||^2 is order-invariant). Inner loop:
//          1 broadcast LDS.128 + 3 FFMA + rare-taken compare.
// Phase 2: one warp per 32 targets; coalesced float4 gather of 3 feats1
//          rows (L2-resident) + RMW accumulate into out (which holds feats2).
// ---------------------------------------------------------------------------
#define KNN_THREADS 256
#define KNN_SMEM (N1 * 16 + KNN_THREADS * 3 * 4 * 2)  // 65536 + 6144 = 71680 B

__global__ __launch_bounds__(KNN_THREADS)
void knn_interp_kernel(const float* __restrict__ xyz2,   // targets [B,N2,3]
                       const float* __restrict__ xyz1,   // sources [B,N1,3]
                       float* __restrict__ out)          // [B,N2,DO], contains feats2
{
    extern __shared__ float smem[];
    float4* sx = (float4*)smem;                    // N1 float4
    float*  sw = smem + N1 * 4;                    // 256*3 weights
    int*    si = (int*)(sw + KNN_THREADS * 3);     // 256*3 indices

    const int b   = blockIdx.y;
    const int tid = threadIdx.x;
    const int t   = blockIdx.x * KNN_THREADS + tid;   // target idx in [0, N2)

    // Load + transform sources into smem
    for (int i = tid; i < N1; i += KNN_THREADS) {
        const float* p = &xyz1[((size_t)b * N1 + i) * 3];
        float x = p[0], y = p[1], z = p[2];
        sx[i] = make_float4(-2.f * x, -2.f * y, -2.f * z, x * x + y * y + z * z);
    }
    __syncthreads();

    const float* tp = &xyz2[((size_t)b * N2 + t) * 3];
    const float txx = tp[0], tyy = tp[1], tzz = tp[2];

    float k0 = 3.4e38f, k1 = 3.4e38f, k2 = 3.4e38f;
    int   i0 = 0, i1 = 0, i2 = 0;

#pragma unroll 4
    for (int s = 0; s < N1; s++) {
        float4 p = sx[s];
        float key = fmaf(p.x, txx, fmaf(p.y, tyy, fmaf(p.z, tzz, p.w)));
        if (key < k2) {
            if (key < k0)      { k2 = k1; i2 = i1; k1 = k0; i1 = i0; k0 = key; i0 = s; }
            else if (key < k1) { k2 = k1; i2 = i1; k1 = key; i1 = s; }
            else               { k2 = key; i2 = s; }
        }
    }

    // Reconstruct reference-form squared distances: d = ||t||^2 + key
    float tt = txx * txx + tyy * tyy + tzz * tzz;
    float d0 = k0 + tt, d1 = k1 + tt, d2 = k2 + tt;
    float w0 = 1.f / (d0 + 1e-8f);
    float w1 = 1.f / (d1 + 1e-8f);
    float w2 = 1.f / (d2 + 1e-8f);
    float wsum = w0 + w1 + w2;
    float inv = 1.f / wsum;
    sw[tid * 3 + 0] = w0 * inv;
    sw[tid * 3 + 1] = w1 * inv;
    sw[tid * 3 + 2] = w2 * inv;
    si[tid * 3 + 0] = i0;
    si[tid * 3 + 1] = i1;
    si[tid * 3 + 2] = i2;
    __syncthreads();

    // Phase 2: warp-cooperative gather + accumulate
    const int warp = tid >> 5, lane = tid & 31;
    const float* fb = g_feats1 + (size_t)b * N1 * DO;

    for (int j = 0; j < 32; j++) {
        int local = warp * 32 + j;
        float ww0 = sw[local * 3 + 0];
        float ww1 = sw[local * 3 + 1];
        float ww2 = sw[local * 3 + 2];
        int   a0  = si[local * 3 + 0];
        int   a1  = si[local * 3 + 1];
        int   a2  = si[local * 3 + 2];
        const float4* f0 = (const float4*)(fb + (size_t)a0 * DO);
        const float4* f1 = (const float4*)(fb + (size_t)a1 * DO);
        const float4* f2 = (const float4*)(fb + (size_t)a2 * DO);
        int tgt = blockIdx.x * KNN_THREADS + local;
        float4* o = (float4*)(out + ((size_t)b * N2 + tgt) * DO);
#pragma unroll
        for (int c = 0; c < 2; c++) {
            int ci = lane * 2 + c;    // DO/4 = 64 float4 per row, 2 per lane
            float4 va = f0[ci], vb = f1[ci], vc = f2[ci], vo = o[ci];
            vo.x += ww0 * va.x + ww1 * vb.x + ww2 * vc.x;
            vo.y += ww0 * va.y + ww1 * vb.y + ww2 * vc.y;
            vo.z += ww0 * va.z + ww1 * vb.z + ww2 * vc.z;
            vo.w += ww0 * va.w + ww1 * vb.w + ww2 * vc.w;
            o[ci] = vo;
        }
    }
}

// ---------------------------------------------------------------------------
extern "C" void kernel_launch(void* const* d_in, const int* in_sizes, int n_in,
                              void* d_out, int out_size)
{
    const float* xyz1    = (const float*)d_in[0];
    const float* points1 = (const float*)d_in[1];
    const float* xyz2    = (const float*)d_in[2];
    const float* points2 = (const float*)d_in[3];
    const float* W1  = (const float*)d_in[4];
    const float* b1  = (const float*)d_in[5];
    const float* g1  = (const float*)d_in[6];
    const float* be1 = (const float*)d_in[7];
    const float* m1  = (const float*)d_in[8];
    const float* v1  = (const float*)d_in[9];
    const float* W2  = (const float*)d_in[10];
    const float* b2  = (const float*)d_in[11];
    const float* g2  = (const float*)d_in[12];
    const float* be2 = (const float*)d_in[13];
    const float* m2  = (const float*)d_in[14];
    const float* v2  = (const float*)d_in[15];
    float* out = (float*)d_out;

    float* feats1;
    cudaGetSymbolAddress((void**)&feats1, g_feats1);

    // K1: feats1 = relu(bn(points1 @ W1^T + b1))   [16384, 256]
    {
        dim3 grid(M1 / BM, DO / BN);
        gemm_bn_relu_kernel<<<grid, 256>>>(points1, W1, b1, g1, be1, m1, v1,
                                           feats1, M1, D1);
    }
    // K2: out = feats2 = relu(bn(points2 @ W2^T + b2))   [65536, 256]
    {
        dim3 grid(M2 / BM, DO / BN);
        gemm_bn_relu_kernel<<<grid, 256>>>(points2, W2, b2, g2, be2, m2, v2,
                                           out, M2, D2);
    }
    // K3: out += interpolate3(xyz2 <- xyz1, feats1)
    {
        cudaFuncSetAttribute(knn_interp_kernel,
                             cudaFuncAttributeMaxDynamicSharedMemorySize,
                             KNN_SMEM);
        dim3 grid(N2 / KNN_THREADS, BATCH);
        knn_interp_kernel<<<grid, KNN_THREADS, KNN_SMEM>>>(xyz2, xyz1, out);
    }
}

// round 5
// speedup vs baseline: 1.4766x; 1.4766x over previous
#include <cuda_runtime.h>
#include <cuda_bf16.h>
#include <cstdint>
#include <math.h>

// Problem constants (fixed shapes from setup_inputs)
#define BATCH   4
#define N1      4096
#define N2      16384
#define D1      512
#define D2      256
#define DO      256
#define M1      (BATCH * N1)   // 16384
#define M2      (BATCH * N2)   // 65536

// ---------------------------------------------------------------------------
// Device scratch (allocation-free rule: __device__ globals)
// ---------------------------------------------------------------------------
__device__ float g_feats1[M1 * DO];                       // 16 MB
__device__ __nv_bfloat16 gA1h[M1 * D1], gA1l[M1 * D1];    // 16 MB each
__device__ __nv_bfloat16 gA2h[M2 * D2], gA2l[M2 * D2];    // 32 MB each
__device__ __nv_bfloat16 gW1h[DO * D1], gW1l[DO * D1];
__device__ __nv_bfloat16 gW2h[DO * D2], gW2l[DO * D2];

// ---------------------------------------------------------------------------
// Helpers
// ---------------------------------------------------------------------------
__device__ __forceinline__ uint32_t smem_u32(const void* p) {
    uint32_t a;
    asm("{ .reg .u64 t; cvta.to.shared.u64 t, %1; cvt.u32.u64 %0, t; }"
        : "=r"(a) : "l"(p));
    return a;
}

#define SWZ(o) ((o) ^ (((o) >> 3) & 0x70))

#define CP16(dst, src) \
    asm volatile("cp.async.cg.shared.global [%0], [%1], 16;" :: "r"(dst), "l"(src) : "memory")
#define CP_COMMIT() asm volatile("cp.async.commit_group;" ::: "memory")
#define CP_WAIT0()  asm volatile("cp.async.wait_group 0;" ::: "memory")
#define CP_WAIT1()  asm volatile("cp.async.wait_group 1;" ::: "memory")

__device__ __forceinline__ void ldsm4(uint32_t r[4], uint32_t addr) {
    asm volatile("ldmatrix.sync.aligned.m8n8.x4.shared.b16 {%0,%1,%2,%3}, [%4];"
        : "=r"(r[0]), "=r"(r[1]), "=r"(r[2]), "=r"(r[3]) : "r"(addr));
}
__device__ __forceinline__ void ldsm2(uint32_t r[2], uint32_t addr) {
    asm volatile("ldmatrix.sync.aligned.m8n8.x2.shared.b16 {%0,%1}, [%2];"
        : "=r"(r[0]), "=r"(r[1]) : "r"(addr));
}
__device__ __forceinline__ void mma_bf16(float d[4], const uint32_t a[4], const uint32_t b[2]) {
    asm volatile("mma.sync.aligned.m16n8k16.row.col.f32.bf16.bf16.f32 "
        "{%0,%1,%2,%3}, {%4,%5,%6,%7}, {%8,%9}, {%0,%1,%2,%3};"
        : "+f"(d[0]), "+f"(d[1]), "+f"(d[2]), "+f"(d[3])
        : "r"(a[0]), "r"(a[1]), "r"(a[2]), "r"(a[3]), "r"(b[0]), "r"(b[1]));
}

// ---------------------------------------------------------------------------
// fp32 -> (hi, lo) bf16 split
// ---------------------------------------------------------------------------
__global__ __launch_bounds__(256)
void split_bf16_kernel(const float* __restrict__ x,
                       __nv_bfloat16* __restrict__ hi,
                       __nv_bfloat16* __restrict__ lo, int n4)
{
    int i = blockIdx.x * blockDim.x + threadIdx.x;
    int stride = gridDim.x * blockDim.x;
    for (; i < n4; i += stride) {
        float4 v = ((const float4*)x)[i];
        __nv_bfloat16 h0 = __float2bfloat16(v.x);
        __nv_bfloat16 h1 = __float2bfloat16(v.y);
        __nv_bfloat16 h2 = __float2bfloat16(v.z);
        __nv_bfloat16 h3 = __float2bfloat16(v.w);
        __nv_bfloat16 l0 = __float2bfloat16(v.x - __bfloat162float(h0));
        __nv_bfloat16 l1 = __float2bfloat16(v.y - __bfloat162float(h1));
        __nv_bfloat16 l2 = __float2bfloat16(v.z - __bfloat162float(h2));
        __nv_bfloat16 l3 = __float2bfloat16(v.w - __bfloat162float(h3));
        ((__nv_bfloat162*)hi)[2 * i + 0] = __nv_bfloat162(h0, h1);
        ((__nv_bfloat162*)hi)[2 * i + 1] = __nv_bfloat162(h2, h3);
        ((__nv_bfloat162*)lo)[2 * i + 0] = __nv_bfloat162(l0, l1);
        ((__nv_bfloat162*)lo)[2 * i + 1] = __nv_bfloat162(l2, l3);
    }
}

// ---------------------------------------------------------------------------
// mma.sync bf16 split GEMM + BN + ReLU.
// C[m,n] = relu((sum_k A[m,k]W[n,k] + bias[n]) * s[n] + sh[n])
// D = AhBh + AhBl + AlBh accumulated in fp32 registers.
// CTA tile 128x128, K-chunk 64 bf16 (SW128 rows), 8 warps (2x4), warp 64x32.
// Double-buffered cp.async.
// ---------------------------------------------------------------------------
#define STAGE 65536u     // Ah 16K | Al 16K | Bh 16K | Bl 16K
#define GEMM_DSMEM (2 * 65536 + 1024)

__device__ __forceinline__ void load_chunk(int tid, int bm, int bn, int K,
                                           uint32_t base, int c,
                                           const __nv_bfloat16* __restrict__ Ah,
                                           const __nv_bfloat16* __restrict__ Al,
                                           const __nv_bfloat16* __restrict__ Bh,
                                           const __nv_bfloat16* __restrict__ Bl)
{
    uint32_t sb = base + (uint32_t)(c & 1) * STAGE;
    int kc = c << 6;
    // A: 128 rows x 64 bf16 (hi + lo)
    for (int i = tid; i < 1024; i += 256) {
        int row = i >> 3, seg = i & 7;
        uint32_t off = SWZ((uint32_t)(row * 128 + seg * 16));
        size_t g = (size_t)(bm + row) * K + kc + seg * 8;
        CP16(sb + off,          (const char*)(Ah + g));
        CP16(sb + 16384u + off, (const char*)(Al + g));
    }
    // B: 128 n-rows x 64 bf16 (hi + lo)
    for (int i = tid; i < 1024; i += 256) {
        int row = i >> 3, seg = i & 7;
        uint32_t off = SWZ((uint32_t)(row * 128 + seg * 16));
        size_t g = (size_t)(bn + row) * K + kc + seg * 8;
        CP16(sb + 32768u + off, (const char*)(Bh + g));
        CP16(sb + 49152u + off, (const char*)(Bl + g));
    }
    CP_COMMIT();
}

__global__ __launch_bounds__(256)
void gemm_mma_kernel(const __nv_bfloat16* __restrict__ Ah,
                     const __nv_bfloat16* __restrict__ Al,
                     const __nv_bfloat16* __restrict__ Bh,
                     const __nv_bfloat16* __restrict__ Bl,
                     const float* __restrict__ bias,
                     const float* __restrict__ gamma,
                     const float* __restrict__ beta,
                     const float* __restrict__ mean,
                     const float* __restrict__ var,
                     float* __restrict__ C, int K)
{
    extern __shared__ char dsm[];
    __shared__ float sScale[128], sShift[128], sBias[128];

    const int tid  = threadIdx.x;
    const int wid  = tid >> 5;
    const int lane = tid & 31;
    const int wm   = wid >> 2;        // 0..1
    const int wn   = wid & 3;         // 0..3
    const int bm   = blockIdx.x * 128;
    const int bn   = blockIdx.y * 128;
    const int NC   = K >> 6;
    uint32_t base  = (smem_u32(dsm) + 1023u) & ~1023u;

    if (tid < 128) {
        int n = bn + tid;
        float sc = gamma[n] * rsqrtf(var[n] + 1e-5f);
        sScale[tid] = sc;
        sShift[tid] = beta[n] - mean[n] * sc;
        sBias[tid]  = bias[n];
    }

    float acc[4][4][4];
#pragma unroll
    for (int mi = 0; mi < 4; mi++)
#pragma unroll
        for (int ni = 0; ni < 4; ni++)
#pragma unroll
            for (int e = 0; e < 4; e++) acc[mi][ni][e] = 0.f;

    load_chunk(tid, bm, bn, K, base, 0, Ah, Al, Bh, Bl);

    // Precompute lane-local ldmatrix offsets (relative, pre-swizzle inputs)
    const int arow  = wm * 64 + (lane & 15);
    const int acolb = (lane >> 4) * 16;
    const int l16   = lane & 15;
    const int brow  = wn * 32 + (l16 & 7);
    const int bcolb = (l16 >> 3) * 16;

    for (int c = 0; c < NC; c++) {
        if (c + 1 < NC) {
            load_chunk(tid, bm, bn, K, base, c + 1, Ah, Al, Bh, Bl);
            CP_WAIT1();
        } else {
            CP_WAIT0();
        }
        __syncthreads();

        uint32_t sb  = base + (uint32_t)(c & 1) * STAGE;
        uint32_t sAh = sb, sAl = sb + 16384u, sBh = sb + 32768u, sBl = sb + 49152u;

#pragma unroll
        for (int kk = 0; kk < 4; kk++) {
            uint32_t ah[4][4], al[4][4], bh[4][2], bl[4][2];
#pragma unroll
            for (int mi = 0; mi < 4; mi++) {
                uint32_t off = SWZ((uint32_t)((arow + mi * 16) * 128 + kk * 32 + acolb));
                ldsm4(ah[mi], sAh + off);
                ldsm4(al[mi], sAl + off);
            }
#pragma unroll
            for (int ni = 0; ni < 4; ni++) {
                uint32_t off = SWZ((uint32_t)((brow + ni * 8) * 128 + kk * 32 + bcolb));
                ldsm2(bh[ni], sBh + off);
                ldsm2(bl[ni], sBl + off);
            }
#pragma unroll
            for (int mi = 0; mi < 4; mi++)
#pragma unroll
                for (int ni = 0; ni < 4; ni++) {
                    mma_bf16(acc[mi][ni], ah[mi], bh[ni]);
                    mma_bf16(acc[mi][ni], ah[mi], bl[ni]);
                    mma_bf16(acc[mi][ni], al[mi], bh[ni]);
                }
        }
        __syncthreads();
    }

    // Epilogue: bias + BN + ReLU, float2 stores
    const int tr = lane >> 2, tq = lane & 3;
#pragma unroll
    for (int mi = 0; mi < 4; mi++) {
        int row0 = bm + wm * 64 + mi * 16 + tr;
#pragma unroll
        for (int ni = 0; ni < 4; ni++) {
            int lc = wn * 32 + ni * 8 + 2 * tq;     // local col 0..127
            int col = bn + lc;
            float s0 = sScale[lc],     s1 = sScale[lc + 1];
            float h0 = sShift[lc],     h1 = sShift[lc + 1];
            float bb0 = sBias[lc],     bb1 = sBias[lc + 1];
            float2 v0, v1;
            v0.x = fmaxf((acc[mi][ni][0] + bb0) * s0 + h0, 0.f);
            v0.y = fmaxf((acc[mi][ni][1] + bb1) * s1 + h1, 0.f);
            v1.x = fmaxf((acc[mi][ni][2] + bb0) * s0 + h0, 0.f);
            v1.y = fmaxf((acc[mi][ni][3] + bb1) * s1 + h1, 0.f);
            *(float2*)&C[(size_t)row0 * DO + col]       = v0;
            *(float2*)&C[(size_t)(row0 + 8) * DO + col] = v1;
        }
    }
}

// ---------------------------------------------------------------------------
// Fused 3-NN + inverse-distance-weighted gather + accumulate (R1, proven).
// ---------------------------------------------------------------------------
#define KNN_THREADS 256
#define KNN_SMEM (N1 * 16 + KNN_THREADS * 3 * 4 * 2)

__global__ __launch_bounds__(KNN_THREADS)
void knn_interp_kernel(const float* __restrict__ xyz2,
                       const float* __restrict__ xyz1,
                       float* __restrict__ out)
{
    extern __shared__ float smem[];
    float4* sx = (float4*)smem;
    float*  sw = smem + N1 * 4;
    int*    si = (int*)(sw + KNN_THREADS * 3);

    const int b   = blockIdx.y;
    const int tid = threadIdx.x;
    const int t   = blockIdx.x * KNN_THREADS + tid;

    for (int i = tid; i < N1; i += KNN_THREADS) {
        const float* p = &xyz1[((size_t)b * N1 + i) * 3];
        float x = p[0], y = p[1], z = p[2];
        sx[i] = make_float4(-2.f * x, -2.f * y, -2.f * z, x * x + y * y + z * z);
    }
    __syncthreads();

    const float* tp = &xyz2[((size_t)b * N2 + t) * 3];
    const float txx = tp[0], tyy = tp[1], tzz = tp[2];

    float k0 = 3.4e38f, k1 = 3.4e38f, k2 = 3.4e38f;
    int   i0 = 0, i1 = 0, i2 = 0;

#pragma unroll 4
    for (int s = 0; s < N1; s++) {
        float4 p = sx[s];
        float key = fmaf(p.x, txx, fmaf(p.y, tyy, fmaf(p.z, tzz, p.w)));
        if (key < k2) {
            if (key < k0)      { k2 = k1; i2 = i1; k1 = k0; i1 = i0; k0 = key; i0 = s; }
            else if (key < k1) { k2 = k1; i2 = i1; k1 = key; i1 = s; }
            else               { k2 = key; i2 = s; }
        }
    }

    float tt = txx * txx + tyy * tyy + tzz * tzz;
    float d0 = k0 + tt, d1 = k1 + tt, d2 = k2 + tt;
    float w0 = 1.f / (d0 + 1e-8f);
    float w1 = 1.f / (d1 + 1e-8f);
    float w2 = 1.f / (d2 + 1e-8f);
    float inv = 1.f / (w0 + w1 + w2);
    sw[tid * 3 + 0] = w0 * inv;
    sw[tid * 3 + 1] = w1 * inv;
    sw[tid * 3 + 2] = w2 * inv;
    si[tid * 3 + 0] = i0;
    si[tid * 3 + 1] = i1;
    si[tid * 3 + 2] = i2;
    __syncthreads();

    const int warp = tid >> 5, lane = tid & 31;
    const float* fb = g_feats1 + (size_t)b * N1 * DO;

    for (int j = 0; j < 32; j++) {
        int local = warp * 32 + j;
        float ww0 = sw[local * 3 + 0];
        float ww1 = sw[local * 3 + 1];
        float ww2 = sw[local * 3 + 2];
        int   a0  = si[local * 3 + 0];
        int   a1  = si[local * 3 + 1];
        int   a2  = si[local * 3 + 2];
        const float4* f0 = (const float4*)(fb + (size_t)a0 * DO);
        const float4* f1 = (const float4*)(fb + (size_t)a1 * DO);
        const float4* f2 = (const float4*)(fb + (size_t)a2 * DO);
        int tgt = blockIdx.x * KNN_THREADS + local;
        float4* o = (float4*)(out + ((size_t)b * N2 + tgt) * DO);
#pragma unroll
        for (int c = 0; c < 2; c++) {
            int ci = lane * 2 + c;
            float4 va = f0[ci], vb = f1[ci], vc = f2[ci], vo = o[ci];
            vo.x += ww0 * va.x + ww1 * vb.x + ww2 * vc.x;
            vo.y += ww0 * va.y + ww1 * vb.y + ww2 * vc.y;
            vo.z += ww0 * va.z + ww1 * vb.z + ww2 * vc.z;
            vo.w += ww0 * va.w + ww1 * vb.w + ww2 * vc.w;
            o[ci] = vo;
        }
    }
}

// ---------------------------------------------------------------------------
extern "C" void kernel_launch(void* const* d_in, const int* in_sizes, int n_in,
                              void* d_out, int out_size)
{
    const float* xyz1    = (const float*)d_in[0];
    const float* points1 = (const float*)d_in[1];
    const float* xyz2    = (const float*)d_in[2];
    const float* points2 = (const float*)d_in[3];
    const float* W1  = (const float*)d_in[4];
    const float* b1  = (const float*)d_in[5];
    const float* g1  = (const float*)d_in[6];
    const float* be1 = (const float*)d_in[7];
    const float* m1  = (const float*)d_in[8];
    const float* v1  = (const float*)d_in[9];
    const float* W2  = (const float*)d_in[10];
    const float* b2  = (const float*)d_in[11];
    const float* g2  = (const float*)d_in[12];
    const float* be2 = (const float*)d_in[13];
    const float* m2  = (const float*)d_in[14];
    const float* v2  = (const float*)d_in[15];
    float* out = (float*)d_out;

    float *feats1;
    __nv_bfloat16 *a1h, *a1l, *a2h, *a2l, *w1h, *w1l, *w2h, *w2l;
    cudaGetSymbolAddress((void**)&feats1, g_feats1);
    cudaGetSymbolAddress((void**)&a1h, gA1h);
    cudaGetSymbolAddress((void**)&a1l, gA1l);
    cudaGetSymbolAddress((void**)&a2h, gA2h);
    cudaGetSymbolAddress((void**)&a2l, gA2l);
    cudaGetSymbolAddress((void**)&w1h, gW1h);
    cudaGetSymbolAddress((void**)&w1l, gW1l);
    cudaGetSymbolAddress((void**)&w2h, gW2h);
    cudaGetSymbolAddress((void**)&w2l, gW2l);

    // Split fp32 -> hi/lo bf16
    split_bf16_kernel<<<2048, 256>>>(points1, a1h, a1l, M1 * D1 / 4);
    split_bf16_kernel<<<4096, 256>>>(points2, a2h, a2l, M2 * D2 / 4);
    split_bf16_kernel<<<128,  256>>>(W1, w1h, w1l, DO * D1 / 4);
    split_bf16_kernel<<<64,   256>>>(W2, w2h, w2l, DO * D2 / 4);

    cudaFuncSetAttribute(gemm_mma_kernel,
                         cudaFuncAttributeMaxDynamicSharedMemorySize, GEMM_DSMEM);

    // K1: feats1 = relu(bn(points1 @ W1^T + b1))   [16384, 256]
    {
        dim3 grid(M1 / 128, DO / 128);
        gemm_mma_kernel<<<grid, 256, GEMM_DSMEM>>>(a1h, a1l, w1h, w1l,
                                                   b1, g1, be1, m1, v1,
                                                   feats1, D1);
    }
    // K2: out = relu(bn(points2 @ W2^T + b2))      [65536, 256]
    {
        dim3 grid(M2 / 128, DO / 128);
        gemm_mma_kernel<<<grid, 256, GEMM_DSMEM>>>(a2h, a2l, w2h, w2l,
                                                   b2, g2, be2, m2, v2,
                                                   out, D2);
    }
    // K3: out += interpolate3(xyz2 <- xyz1, feats1)
    cudaFuncSetAttribute(knn_interp_kernel,
                         cudaFuncAttributeMaxDynamicSharedMemorySize, KNN_SMEM);
    dim3 grid(N2 / KNN_THREADS, BATCH);
    knn_interp_kernel<<<grid, KNN_THREADS, KNN_SMEM>>>(xyz2, xyz1, out);
}